// round 9
// baseline (speedup 1.0000x reference)
#include <cuda_runtime.h>
#include <cstdint>
#include <math.h>

#define BB 8
#define SS 2048
#define EE 1024
#define DD 64
#define NSEG 3              // split-KV segments

// q (all rows) and k,v (COMPACTED rows) as bf16 hi/lo planes, 2 bf16 per u32
__device__ unsigned int g_qh[BB * SS * DD / 2];
__device__ unsigned int g_ql[BB * SS * DD / 2];
__device__ unsigned int g_kh[BB * SS * DD / 2];
__device__ unsigned int g_kl[BB * SS * DD / 2];
__device__ unsigned int g_vh[BB * SS * DD / 2];
__device__ unsigned int g_vl[BB * SS * DD / 2];

// W planes (bf16 hi/lo), [mat][n][k/2] u32
__device__ unsigned int g_Wh[3 * 64 * 512];
__device__ unsigned int g_Wl[3 * 64 * 512];

// mask compaction
__device__ int g_kidx[BB][SS];
__device__ int g_kcnt[BB];

// split-KV partials
__device__ float g_Op[NSEG][BB * SS * DD];
__device__ float g_mp[NSEG][BB * SS];
__device__ float g_lp[NSEG][BB * SS];

// ---------------------------------------------------------------------------
// helpers
// ---------------------------------------------------------------------------
__device__ __forceinline__ uint32_t smem_u32(const void* p) {
    return (uint32_t)__cvta_generic_to_shared(p);
}

__device__ __forceinline__ void ldsm_x4(uint32_t addr, uint32_t& r0, uint32_t& r1,
                                        uint32_t& r2, uint32_t& r3) {
    asm volatile("ldmatrix.sync.aligned.m8n8.x4.shared.b16 {%0,%1,%2,%3}, [%4];"
                 : "=r"(r0), "=r"(r1), "=r"(r2), "=r"(r3) : "r"(addr));
}

__device__ __forceinline__ void ldsm_x4_t(uint32_t addr, uint32_t& r0, uint32_t& r1,
                                          uint32_t& r2, uint32_t& r3) {
    asm volatile("ldmatrix.sync.aligned.m8n8.x4.trans.shared.b16 {%0,%1,%2,%3}, [%4];"
                 : "=r"(r0), "=r"(r1), "=r"(r2), "=r"(r3) : "r"(addr));
}

__device__ __forceinline__ void mma_bf16(float c[4],
                                         uint32_t a0, uint32_t a1, uint32_t a2, uint32_t a3,
                                         uint32_t b0, uint32_t b1) {
    asm volatile("mma.sync.aligned.m16n8k16.row.col.f32.bf16.bf16.f32 "
                 "{%0,%1,%2,%3}, {%4,%5,%6,%7}, {%8,%9}, {%0,%1,%2,%3};"
                 : "+f"(c[0]), "+f"(c[1]), "+f"(c[2]), "+f"(c[3])
                 : "r"(a0), "r"(a1), "r"(a2), "r"(a3), "r"(b0), "r"(b1));
}

__device__ __forceinline__ uint32_t pack2(float x0, float x1) {
    uint32_t h;
    asm("cvt.rn.bf16x2.f32 %0, %1, %2;" : "=r"(h) : "f"(x1), "f"(x0));
    return h;
}

__device__ __forceinline__ void split_pair(float x0, float x1, uint32_t& hi, uint32_t& lo) {
    hi = pack2(x0, x1);
    float h0 = __uint_as_float(hi << 16);
    float h1 = __uint_as_float(hi & 0xffff0000u);
    lo = pack2(x0 - h0, x1 - h1);
}

__device__ __forceinline__ void cp16(uint32_t s, const void* g) {
    asm volatile("cp.async.cg.shared.global [%0], [%1], 16;" :: "r"(s), "l"(g));
}

// ---------------------------------------------------------------------------
// prep kernels
// ---------------------------------------------------------------------------
__global__ void prep_w(const float* __restrict__ Wq, const float* __restrict__ Wk,
                       const float* __restrict__ Wv) {
    int idx = blockIdx.x * 256 + threadIdx.x;
    int mat = idx >> 15;
    int off = idx & 32767;
    const float* W = (mat == 0) ? Wq : (mat == 1) ? Wk : Wv;
    float2 v = reinterpret_cast<const float2*>(W)[off];
    uint32_t h, l;
    split_pair(v.x, v.y, h, l);
    g_Wh[idx] = h;
    g_Wl[idx] = l;
}

__global__ void prep_mask(const int* __restrict__ mask) {
    const int b = blockIdx.x;
    const int t = threadIdx.x;
    __shared__ int wsum[8];
    const int* mrow = mask + (size_t)b * SS;

    int um[8], loc[8], cnt = 0;
    #pragma unroll
    for (int j = 0; j < 8; j++) {
        int s = t * 8 + j;
        um[j] = (mrow[s] == 0);
        loc[j] = cnt;
        cnt += um[j];
    }
    const int lane = t & 31, w = t >> 5;
    int inc = cnt;
    #pragma unroll
    for (int off = 1; off < 32; off <<= 1) {
        int n = __shfl_up_sync(0xffffffffu, inc, off);
        if (lane >= off) inc += n;
    }
    if (lane == 31) wsum[w] = inc;
    __syncthreads();
    int wbase = 0;
    #pragma unroll
    for (int i = 0; i < 8; i++)
        if (i < w) wbase += wsum[i];
    const int base = wbase + inc - cnt;
    #pragma unroll
    for (int j = 0; j < 8; j++)
        if (um[j]) g_kidx[b][base + loc[j]] = t * 8 + j;
    if (t == 255) g_kcnt[b] = base + cnt;
}

// ---------------------------------------------------------------------------
// Projection kernel, templated on NMAT:
//   NMAT=1: Q projection, all rows. grid.x = 256 tiles of 64 rows.
//   NMAT=2: K+V projection, GATHERED unmasked rows, compacted output.
//           grid (32, BB); tiles with j0 >= nk exit early.
// BM=64, BK=32, 256 threads (8 warps: 4 M x 2 N). W planes via cp.async
// double-buffer; x rows via f32 register prefetch + in-register bf16 split.
// ---------------------------------------------------------------------------
#define QP 40
#define XPL (64 * QP)            // u16 per plane
#define XSTG (2 * XPL)
#define WBASE (2 * XSTG)
#define PROJ_SMEM_BYTES(nmat) ((WBASE + 2 * 2 * (nmat) * XPL) * 2)

template<int NMAT>
__global__ __launch_bounds__(256) void proj_kernel(
    const float* __restrict__ x,
    const float* __restrict__ bq, const float* __restrict__ bk,
    const float* __restrict__ bv)
{
    extern __shared__ unsigned short qsm[];
    constexpr int MATLO = (NMAT == 1) ? 0 : 1;
    constexpr int WSTGP = 2 * NMAT;          // W planes per stage

    const int t = threadIdx.x;
    const int warp = t >> 5, lane = t & 31;
    const int wm = warp >> 1;
    const int wn = warp & 1;

    int b = 0, j0 = 0, nk = 0, m0 = 0;
    if (NMAT == 1) {
        m0 = blockIdx.x * 64;
    } else {
        b = blockIdx.y;
        j0 = blockIdx.x * 64;
        nk = g_kcnt[b];
        if (j0 >= nk) return;
    }

    float acc[NMAT][4][4] = {};

    const int arow = wm * 16 + (lane & 15);
    const int acol = (lane >> 4) * 8;
    const int brow = (lane & 7) + ((lane >> 4) << 3);
    const int bcol = ((lane >> 3) & 1) * 8;

    const int xr = t >> 2;             // staged row within tile
    const int xc = (t & 3) * 8;        // f32 col base

    // resolve this thread's source x row pointer once
    const float* xrow;
    if (NMAT == 1) {
        xrow = x + (size_t)(m0 + xr) * EE;
    } else {
        int j = j0 + xr;
        if (j > nk - 1) j = nk - 1;    // clamp: tail dup rows, masked downstream
        xrow = x + ((size_t)b * SS + g_kidx[b][j]) * EE;
    }

    // W stage s for k-slab `slab`: 2*NMAT planes x 256 chunks of 16B each.
    // chunk c in [0,256): row = c>>2 (0..63), c4 = c&3 -> 4 x 16B per row.
    // All smem/gmem offsets 16B aligned (R5-proven mapping).
    auto issue_w = [&](int s, int slab) {
        #pragma unroll
        for (int i = 0; i < 2 * NMAT; i++) {
            int chunk = t + i * 256;
            int p = chunk >> 8, c = chunk & 255;
            int row = c >> 2, c4 = c & 3;
            uint32_t dst = smem_u32(&qsm[WBASE + (s * WSTGP + p) * XPL + row * QP + c4 * 8]);
            const unsigned int* srcp = (p & 1) ? g_Wl : g_Wh;
            cp16(dst, srcp + ((size_t)(MATLO + (p >> 1)) * 32768
                              + (size_t)row * 512 + slab * 16 + c4 * 4));
        }
        asm volatile("cp.async.commit_group;");
    };

    auto sts_x = [&](int s, float4 a0, float4 a1) {
        unsigned short* Xh = qsm + s * XSTG;
        unsigned short* Xl = Xh + XPL;
        uint32_t h, l;
        split_pair(a0.x, a0.y, h, l);
        *(uint32_t*)&Xh[xr * QP + xc]     = h; *(uint32_t*)&Xl[xr * QP + xc]     = l;
        split_pair(a0.z, a0.w, h, l);
        *(uint32_t*)&Xh[xr * QP + xc + 2] = h; *(uint32_t*)&Xl[xr * QP + xc + 2] = l;
        split_pair(a1.x, a1.y, h, l);
        *(uint32_t*)&Xh[xr * QP + xc + 4] = h; *(uint32_t*)&Xl[xr * QP + xc + 4] = l;
        split_pair(a1.z, a1.w, h, l);
        *(uint32_t*)&Xh[xr * QP + xc + 6] = h; *(uint32_t*)&Xl[xr * QP + xc + 6] = l;
    };

    issue_w(0, 0);
    {
        float4 a0 = *reinterpret_cast<const float4*>(&xrow[xc]);
        float4 a1 = *reinterpret_cast<const float4*>(&xrow[xc + 4]);
        sts_x(0, a0, a1);
    }
    float4 xa0 = *reinterpret_cast<const float4*>(&xrow[32 + xc]);
    float4 xa1 = *reinterpret_cast<const float4*>(&xrow[32 + xc + 4]);

    const int NI = EE / 32;
    for (int i = 0; i < NI; i++) {
        const int s = i & 1;

        asm volatile("cp.async.wait_group 0;");
        __syncthreads();

        if (i + 1 < NI) {
            issue_w(s ^ 1, i + 1);
            sts_x(s ^ 1, xa0, xa1);
            if (i + 2 < NI) {
                int kn = (i + 2) * 32;
                xa0 = *reinterpret_cast<const float4*>(&xrow[kn + xc]);
                xa1 = *reinterpret_cast<const float4*>(&xrow[kn + xc + 4]);
            }
        }

        const unsigned short* Xh = qsm + s * XSTG;
        const unsigned short* Xl = Xh + XPL;
        const unsigned short* Wb = qsm + WBASE + s * WSTGP * XPL;

        #pragma unroll
        for (int ks = 0; ks < 2; ks++) {
            uint32_t ah[4], al[4];
            ldsm_x4(smem_u32(&Xh[arow * QP + ks * 16 + acol]), ah[0], ah[1], ah[2], ah[3]);
            ldsm_x4(smem_u32(&Xl[arow * QP + ks * 16 + acol]), al[0], al[1], al[2], al[3]);
            #pragma unroll
            for (int mm = 0; mm < NMAT; mm++) {
                const unsigned short* Wh = Wb + (mm * 2) * XPL;
                const unsigned short* Wl = Wh + XPL;
                #pragma unroll
                for (int pr = 0; pr < 2; pr++) {
                    uint32_t bh0, bh1, bh2, bh3, bl0, bl1, bl2, bl3;
                    ldsm_x4(smem_u32(&Wh[(wn * 32 + pr * 16 + brow) * QP + ks * 16 + bcol]),
                            bh0, bh1, bh2, bh3);
                    ldsm_x4(smem_u32(&Wl[(wn * 32 + pr * 16 + brow) * QP + ks * 16 + bcol]),
                            bl0, bl1, bl2, bl3);
                    float* c0 = acc[mm][pr * 2];
                    float* c1 = acc[mm][pr * 2 + 1];
                    mma_bf16(c0, ah[0], ah[1], ah[2], ah[3], bh0, bh1);
                    mma_bf16(c0, ah[0], ah[1], ah[2], ah[3], bl0, bl1);
                    mma_bf16(c0, al[0], al[1], al[2], al[3], bh0, bh1);
                    mma_bf16(c1, ah[0], ah[1], ah[2], ah[3], bh2, bh3);
                    mma_bf16(c1, ah[0], ah[1], ah[2], ah[3], bl2, bl3);
                    mma_bf16(c1, al[0], al[1], al[2], al[3], bh2, bh3);
                }
            }
        }
    }

    // epilogue
    #pragma unroll
    for (int mm = 0; mm < NMAT; mm++) {
        const int mat = MATLO + mm;
        const float* bias = (mat == 0) ? bq : (mat == 1) ? bk : bv;
        unsigned int* gh = (mat == 0) ? g_qh : (mat == 1) ? g_kh : g_vh;
        unsigned int* gl = (mat == 0) ? g_ql : (mat == 1) ? g_kl : g_vl;
        const size_t obase = (NMAT == 1) ? (size_t)m0 : ((size_t)b * SS + j0);
        #pragma unroll
        for (int na = 0; na < 4; na++) {
            int col  = wn * 32 + na * 8 + (lane & 3) * 2;
            size_t row0 = obase + wm * 16 + (lane >> 2);
            float b0 = bias[col], b1 = bias[col + 1];
            float c0 = acc[mm][na][0] + b0, c1 = acc[mm][na][1] + b1;
            float c2 = acc[mm][na][2] + b0, c3 = acc[mm][na][3] + b1;
            uint32_t h, l;
            split_pair(c0, c1, h, l);
            gh[row0 * 32 + col / 2] = h;
            gl[row0 * 32 + col / 2] = l;
            split_pair(c2, c3, h, l);
            gh[(row0 + 8) * 32 + col / 2] = h;
            gl[(row0 + 8) * 32 + col / 2] = l;
        }
    }
}

// ---------------------------------------------------------------------------
// Flash attention over COMPACTED keys (contiguous), split-KV x3.
// 128 threads (4 warps), q-tile 64, key-tile 64. cp.async double-buffered;
// V via ldmatrix.trans. Stores UNNORMALIZED partial O + (m,l).
// ---------------------------------------------------------------------------
#define KP 72
#define TILE_U16 (64 * KP)
#define STAGE_U16 (4 * TILE_U16)
#define ATTN_SMEM_BYTES (2 * STAGE_U16 * 2 + 64 * 4)

__device__ __forceinline__ void stage_tile(uint32_t sbase, size_t gbase, int t) {
    #pragma unroll
    for (int i = 0; i < 4; i++) {
        int chunk = t + i * 128;
        int r = chunk >> 3, c = chunk & 7;
        uint32_t soff = (uint32_t)(r * KP + c * 8) * 2;
        size_t goff = (size_t)r * 32 + c * 4;
        cp16(sbase + soff,                     g_kh + gbase + goff);
        cp16(sbase + TILE_U16 * 2 + soff,      g_kl + gbase + goff);
        cp16(sbase + 2 * TILE_U16 * 2 + soff,  g_vh + gbase + goff);
        cp16(sbase + 3 * TILE_U16 * 2 + soff,  g_vl + gbase + goff);
    }
    asm volatile("cp.async.commit_group;");
}

__global__ __launch_bounds__(128, 3) void attn_kernel()
{
    extern __shared__ unsigned short sm[];
    float* ms = (float*)(sm + 2 * STAGE_U16);

    const int t = threadIdx.x, warp = t >> 5, lane = t & 31;
    const int b = blockIdx.y, q0 = blockIdx.x * 64;
    const int seg = blockIdx.z;

    const int nk = g_kcnt[b];
    const int T = (nk + 63) >> 6;
    const int bnt = T / 3, rem = T - bnt * 3;
    const int nt = bnt + (seg < rem ? 1 : 0);
    const int t0 = seg * bnt + (seg < rem ? seg : rem);

    // --- stage Q into stage-0, extract fragments ---
    {
        uint32_t s0 = smem_u32(sm);
        size_t gq = ((size_t)b * SS + q0) * 32;
        #pragma unroll
        for (int i = 0; i < 4; i++) {
            int chunk = t + i * 128;
            int r = chunk >> 3, c = chunk & 7;
            uint32_t soff = (uint32_t)(r * KP + c * 8) * 2;
            size_t goff = (size_t)r * 32 + c * 4;
            cp16(s0 + soff,                g_qh + gq + goff);
            cp16(s0 + TILE_U16 * 2 + soff, g_ql + gq + goff);
        }
        asm volatile("cp.async.commit_group;");
        asm volatile("cp.async.wait_group 0;");
        __syncthreads();
    }

    uint32_t qh[4][4], ql[4][4];
    {
        const int arow = warp * 16 + (lane & 15);
        const int acol = (lane >> 4) * 8;
        #pragma unroll
        for (int ks = 0; ks < 4; ks++) {
            ldsm_x4(smem_u32(&sm[arow * KP + ks * 16 + acol]),
                    qh[ks][0], qh[ks][1], qh[ks][2], qh[ks][3]);
            ldsm_x4(smem_u32(&sm[TILE_U16 + arow * KP + ks * 16 + acol]),
                    ql[ks][0], ql[ks][1], ql[ks][2], ql[ks][3]);
        }
    }
    __syncthreads();

    float O[8][4] = {};
    float m0r = -INFINITY, m1r = -INFINITY, l0r = 0.f, l1r = 0.f;
    const float scale = 0.125f;

    const uint32_t stage_addr[2] = { smem_u32(sm), smem_u32(sm + STAGE_U16) };

    if (nt > 0) {
        stage_tile(stage_addr[0], ((size_t)b * SS + t0 * 64) * 32, t);

        const int brow = (lane & 7) + ((lane >> 4) << 3);
        const int bco  = ((lane >> 3) & 1) * 8;
        const int vrow = lane & 15;
        const int vco  = (lane >> 4) * 8;

        for (int it = 0; it < nt; ++it) {
            const int st = it & 1;
            const unsigned short* Kh = sm + st * STAGE_U16;
            const unsigned short* Kl = Kh + TILE_U16;
            const unsigned short* Vh = Kh + 2 * TILE_U16;
            const unsigned short* Vl = Kh + 3 * TILE_U16;

            if (it + 1 < nt)
                stage_tile(stage_addr[st ^ 1], ((size_t)b * SS + (t0 + it + 1) * 64) * 32, t);
            if (t < 64) ms[t] = ((t0 + it) * 64 + t < nk) ? 0.f : -INFINITY;

            if (it + 1 < nt) asm volatile("cp.async.wait_group 1;");
            else             asm volatile("cp.async.wait_group 0;");
            __syncthreads();

            // --- S = Q K^T ---
            float S[8][4] = {};
            #pragma unroll
            for (int ks = 0; ks < 4; ks++) {
                #pragma unroll
                for (int pr = 0; pr < 4; pr++) {
                    uint32_t bh0, bh1, bh2, bh3, bl0, bl1, bl2, bl3;
                    ldsm_x4(smem_u32(&Kh[(pr * 16 + brow) * KP + ks * 16 + bco]),
                            bh0, bh1, bh2, bh3);
                    ldsm_x4(smem_u32(&Kl[(pr * 16 + brow) * KP + ks * 16 + bco]),
                            bl0, bl1, bl2, bl3);
                    float* s0 = S[pr * 2];
                    float* s1 = S[pr * 2 + 1];
                    mma_bf16(s0, qh[ks][0], qh[ks][1], qh[ks][2], qh[ks][3], bh0, bh1);
                    mma_bf16(s0, qh[ks][0], qh[ks][1], qh[ks][2], qh[ks][3], bl0, bl1);
                    mma_bf16(s0, ql[ks][0], ql[ks][1], ql[ks][2], ql[ks][3], bh0, bh1);
                    mma_bf16(s1, qh[ks][0], qh[ks][1], qh[ks][2], qh[ks][3], bh2, bh3);
                    mma_bf16(s1, qh[ks][0], qh[ks][1], qh[ks][2], qh[ks][3], bl2, bl3);
                    mma_bf16(s1, ql[ks][0], ql[ks][1], ql[ks][2], ql[ks][3], bh2, bh3);
                }
            }

            // --- online softmax ---
            float rmax0 = -INFINITY, rmax1 = -INFINITY;
            #pragma unroll
            for (int na = 0; na < 8; na++) {
                int col = na * 8 + (lane & 3) * 2;
                float ma = ms[col], mb = ms[col + 1];
                S[na][0] = S[na][0] * scale + ma;
                S[na][1] = S[na][1] * scale + mb;
                S[na][2] = S[na][2] * scale + ma;
                S[na][3] = S[na][3] * scale + mb;
                rmax0 = fmaxf(rmax0, fmaxf(S[na][0], S[na][1]));
                rmax1 = fmaxf(rmax1, fmaxf(S[na][2], S[na][3]));
            }
            rmax0 = fmaxf(rmax0, __shfl_xor_sync(0xffffffffu, rmax0, 1));
            rmax0 = fmaxf(rmax0, __shfl_xor_sync(0xffffffffu, rmax0, 2));
            rmax1 = fmaxf(rmax1, __shfl_xor_sync(0xffffffffu, rmax1, 1));
            rmax1 = fmaxf(rmax1, __shfl_xor_sync(0xffffffffu, rmax1, 2));

            float nm0 = fmaxf(m0r, rmax0), nm1 = fmaxf(m1r, rmax1);
            float f0 = (m0r == -INFINITY) ? 0.f : __expf(m0r - nm0);
            float f1 = (m1r == -INFINITY) ? 0.f : __expf(m1r - nm1);
            float rs0 = 0.f, rs1 = 0.f;
            #pragma unroll
            for (int na = 0; na < 8; na++) {
                float p0 = __expf(S[na][0] - nm0); p0 = (S[na][0] == -INFINITY) ? 0.f : p0;
                float p1 = __expf(S[na][1] - nm0); p1 = (S[na][1] == -INFINITY) ? 0.f : p1;
                float p2 = __expf(S[na][2] - nm1); p2 = (S[na][2] == -INFINITY) ? 0.f : p2;
                float p3 = __expf(S[na][3] - nm1); p3 = (S[na][3] == -INFINITY) ? 0.f : p3;
                S[na][0] = p0; S[na][1] = p1; S[na][2] = p2; S[na][3] = p3;
                rs0 += p0 + p1; rs1 += p2 + p3;
            }
            rs0 += __shfl_xor_sync(0xffffffffu, rs0, 1);
            rs0 += __shfl_xor_sync(0xffffffffu, rs0, 2);
            rs1 += __shfl_xor_sync(0xffffffffu, rs1, 1);
            rs1 += __shfl_xor_sync(0xffffffffu, rs1, 2);
            l0r = l0r * f0 + rs0;  m0r = nm0;
            l1r = l1r * f1 + rs1;  m1r = nm1;

            #pragma unroll
            for (int na = 0; na < 8; na++) {
                O[na][0] *= f0; O[na][1] *= f0;
                O[na][2] *= f1; O[na][3] *= f1;
            }

            // --- O += P V ---
            #pragma unroll
            for (int kk = 0; kk < 4; kk++) {
                uint32_t ph[4], pl[4];
                split_pair(S[2 * kk][0],     S[2 * kk][1],     ph[0], pl[0]);
                split_pair(S[2 * kk][2],     S[2 * kk][3],     ph[1], pl[1]);
                split_pair(S[2 * kk + 1][0], S[2 * kk + 1][1], ph[2], pl[2]);
                split_pair(S[2 * kk + 1][2], S[2 * kk + 1][3], ph[3], pl[3]);
                #pragma unroll
                for (int pr = 0; pr < 4; pr++) {
                    uint32_t bh0, bh1, bh2, bh3, bl0, bl1, bl2, bl3;
                    ldsm_x4_t(smem_u32(&Vh[(kk * 16 + vrow) * KP + pr * 16 + vco]),
                              bh0, bh1, bh2, bh3);
                    ldsm_x4_t(smem_u32(&Vl[(kk * 16 + vrow) * KP + pr * 16 + vco]),
                              bl0, bl1, bl2, bl3);
                    float* o0 = O[pr * 2];
                    float* o1 = O[pr * 2 + 1];
                    mma_bf16(o0, ph[0], ph[1], ph[2], ph[3], bh0, bh1);
                    mma_bf16(o0, ph[0], ph[1], ph[2], ph[3], bl0, bl1);
                    mma_bf16(o0, pl[0], pl[1], pl[2], pl[3], bh0, bh1);
                    mma_bf16(o1, ph[0], ph[1], ph[2], ph[3], bh2, bh3);
                    mma_bf16(o1, ph[0], ph[1], ph[2], ph[3], bl2, bl3);
                    mma_bf16(o1, pl[0], pl[1], pl[2], pl[3], bh2, bh3);
                }
            }
            __syncthreads();
        }
    }

    // --- store UNNORMALIZED partials + (m,l) ---
    int row0 = q0 + warp * 16 + (lane >> 2);
    float* Op = g_Op[seg];
    #pragma unroll
    for (int na = 0; na < 8; na++) {
        int col = na * 8 + (lane & 3) * 2;
        *(float2*)&Op[((size_t)b * SS + row0) * DD + col] =
            make_float2(O[na][0], O[na][1]);
        *(float2*)&Op[((size_t)b * SS + row0 + 8) * DD + col] =
            make_float2(O[na][2], O[na][3]);
    }
    if ((lane & 3) == 0) {
        size_t r = (size_t)b * SS + row0;
        g_mp[seg][r] = m0r;     g_lp[seg][r] = l0r;
        g_mp[seg][r + 8] = m1r; g_lp[seg][r + 8] = l1r;
    }
}

// ---------------------------------------------------------------------------
// combine split-KV partials (3-way)
// ---------------------------------------------------------------------------
__global__ void combine_kernel(float* __restrict__ out) {
    int idx = blockIdx.x * 256 + threadIdx.x;
    int row = idx >> 4;
    float m0 = g_mp[0][row], m1 = g_mp[1][row], m2 = g_mp[2][row];
    float M = fmaxf(fmaxf(m0, m1), m2);
    float w0 = (m0 == -INFINITY) ? 0.f : __expf(m0 - M);
    float w1 = (m1 == -INFINITY) ? 0.f : __expf(m1 - M);
    float w2 = (m2 == -INFINITY) ? 0.f : __expf(m2 - M);
    float inv = 1.f / (w0 * g_lp[0][row] + w1 * g_lp[1][row] + w2 * g_lp[2][row]);
    float a0 = w0 * inv, a1 = w1 * inv, a2 = w2 * inv;
    float4 o0 = reinterpret_cast<const float4*>(g_Op[0])[idx];
    float4 o1 = reinterpret_cast<const float4*>(g_Op[1])[idx];
    float4 o2 = reinterpret_cast<const float4*>(g_Op[2])[idx];
    float4 r;
    r.x = o0.x * a0 + o1.x * a1 + o2.x * a2;
    r.y = o0.y * a0 + o1.y * a1 + o2.y * a2;
    r.z = o0.z * a0 + o1.z * a1 + o2.z * a2;
    r.w = o0.w * a0 + o1.w * a1 + o2.w * a2;
    reinterpret_cast<float4*>(out)[idx] = r;
}

// ---------------------------------------------------------------------------
// Launch
// ---------------------------------------------------------------------------
extern "C" void kernel_launch(void* const* d_in, const int* in_sizes, int n_in,
                              void* d_out, int out_size) {
    const float* x  = (const float*)d_in[0];
    const float* Wq = (const float*)d_in[1];
    const float* bq = (const float*)d_in[2];
    const float* Wk = (const float*)d_in[3];
    const float* bk = (const float*)d_in[4];
    const float* Wv = (const float*)d_in[5];
    const float* bv = (const float*)d_in[6];
    const int*   pm = (const int*)d_in[7];
    float* out = (float*)d_out;

    prep_w<<<3 * 64 * 512 / 256, 256>>>(Wq, Wk, Wv);
    prep_mask<<<BB, 256>>>(pm);

    cudaFuncSetAttribute(proj_kernel<1>, cudaFuncAttributeMaxDynamicSharedMemorySize,
                         PROJ_SMEM_BYTES(1));
    cudaFuncSetAttribute(proj_kernel<2>, cudaFuncAttributeMaxDynamicSharedMemorySize,
                         PROJ_SMEM_BYTES(2));
    proj_kernel<2><<<dim3(SS / 64, BB), 256, PROJ_SMEM_BYTES(2)>>>(x, bq, bk, bv);
    proj_kernel<1><<<BB * SS / 64, 256, PROJ_SMEM_BYTES(1)>>>(x, bq, bk, bv);

    cudaFuncSetAttribute(attn_kernel, cudaFuncAttributeMaxDynamicSharedMemorySize,
                         ATTN_SMEM_BYTES);
    attn_kernel<<<dim3(SS / 64, BB, NSEG), 128, ATTN_SMEM_BYTES>>>();

    combine_kernel<<<BB * SS * DD / 4 / 256, 256>>>(out);
}

// round 10
// speedup vs baseline: 1.0964x; 1.0964x over previous
#include <cuda_runtime.h>
#include <cstdint>
#include <math.h>

#define BB 8
#define SS 2048
#define EE 1024
#define DD 64
#define NSEG 3              // split-KV segments

// q (all rows, scattered) and k,v (COMPACTED rows) as bf16 hi/lo planes
__device__ unsigned int g_qh[BB * SS * DD / 2];
__device__ unsigned int g_ql[BB * SS * DD / 2];
__device__ unsigned int g_kh[BB * SS * DD / 2];
__device__ unsigned int g_kl[BB * SS * DD / 2];
__device__ unsigned int g_vh[BB * SS * DD / 2];
__device__ unsigned int g_vl[BB * SS * DD / 2];

// W planes (bf16 hi/lo), [mat][n][k/2] u32
__device__ unsigned int g_Wh[3 * 64 * 512];
__device__ unsigned int g_Wl[3 * 64 * 512];

// mask compaction: unmasked list, masked list, unmasked count
__device__ int g_kidx[BB][SS];
__device__ int g_midx[BB][SS];
__device__ int g_kcnt[BB];

// split-KV partials
__device__ float g_Op[NSEG][BB * SS * DD];
__device__ float g_mp[NSEG][BB * SS];
__device__ float g_lp[NSEG][BB * SS];

// ---------------------------------------------------------------------------
// helpers
// ---------------------------------------------------------------------------
__device__ __forceinline__ uint32_t smem_u32(const void* p) {
    return (uint32_t)__cvta_generic_to_shared(p);
}

__device__ __forceinline__ void ldsm_x4(uint32_t addr, uint32_t& r0, uint32_t& r1,
                                        uint32_t& r2, uint32_t& r3) {
    asm volatile("ldmatrix.sync.aligned.m8n8.x4.shared.b16 {%0,%1,%2,%3}, [%4];"
                 : "=r"(r0), "=r"(r1), "=r"(r2), "=r"(r3) : "r"(addr));
}

__device__ __forceinline__ void ldsm_x4_t(uint32_t addr, uint32_t& r0, uint32_t& r1,
                                          uint32_t& r2, uint32_t& r3) {
    asm volatile("ldmatrix.sync.aligned.m8n8.x4.trans.shared.b16 {%0,%1,%2,%3}, [%4];"
                 : "=r"(r0), "=r"(r1), "=r"(r2), "=r"(r3) : "r"(addr));
}

__device__ __forceinline__ void mma_bf16(float c[4],
                                         uint32_t a0, uint32_t a1, uint32_t a2, uint32_t a3,
                                         uint32_t b0, uint32_t b1) {
    asm volatile("mma.sync.aligned.m16n8k16.row.col.f32.bf16.bf16.f32 "
                 "{%0,%1,%2,%3}, {%4,%5,%6,%7}, {%8,%9}, {%0,%1,%2,%3};"
                 : "+f"(c[0]), "+f"(c[1]), "+f"(c[2]), "+f"(c[3])
                 : "r"(a0), "r"(a1), "r"(a2), "r"(a3), "r"(b0), "r"(b1));
}

__device__ __forceinline__ uint32_t pack2(float x0, float x1) {
    uint32_t h;
    asm("cvt.rn.bf16x2.f32 %0, %1, %2;" : "=r"(h) : "f"(x1), "f"(x0));
    return h;
}

__device__ __forceinline__ void split_pair(float x0, float x1, uint32_t& hi, uint32_t& lo) {
    hi = pack2(x0, x1);
    float h0 = __uint_as_float(hi << 16);
    float h1 = __uint_as_float(hi & 0xffff0000u);
    lo = pack2(x0 - h0, x1 - h1);
}

__device__ __forceinline__ void cp16(uint32_t s, const void* g) {
    asm volatile("cp.async.cg.shared.global [%0], [%1], 16;" :: "r"(s), "l"(g));
}

// ---------------------------------------------------------------------------
// prep kernels
// ---------------------------------------------------------------------------
__global__ void prep_w(const float* __restrict__ Wq, const float* __restrict__ Wk,
                       const float* __restrict__ Wv) {
    int idx = blockIdx.x * 256 + threadIdx.x;
    int mat = idx >> 15;
    int off = idx & 32767;
    const float* W = (mat == 0) ? Wq : (mat == 1) ? Wk : Wv;
    float2 v = reinterpret_cast<const float2*>(W)[off];
    uint32_t h, l;
    split_pair(v.x, v.y, h, l);
    g_Wh[idx] = h;
    g_Wl[idx] = l;
}

__global__ void prep_mask(const int* __restrict__ mask) {
    const int b = blockIdx.x;
    const int t = threadIdx.x;
    __shared__ int wsum[8];
    const int* mrow = mask + (size_t)b * SS;

    int um[8], loc[8], cnt = 0;
    #pragma unroll
    for (int j = 0; j < 8; j++) {
        int s = t * 8 + j;
        um[j] = (mrow[s] == 0);
        loc[j] = cnt;
        cnt += um[j];
    }
    const int lane = t & 31, w = t >> 5;
    int inc = cnt;
    #pragma unroll
    for (int off = 1; off < 32; off <<= 1) {
        int n = __shfl_up_sync(0xffffffffu, inc, off);
        if (lane >= off) inc += n;
    }
    if (lane == 31) wsum[w] = inc;
    __syncthreads();
    int wbase = 0;
    #pragma unroll
    for (int i = 0; i < 8; i++)
        if (i < w) wbase += wsum[i];
    const int base = wbase + inc - cnt;
    #pragma unroll
    for (int j = 0; j < 8; j++) {
        int s = t * 8 + j;
        int u = base + loc[j];          // unmasked strictly before s
        if (um[j]) g_kidx[b][u] = s;
        else       g_midx[b][s - u] = s;
    }
    if (t == 255) g_kcnt[b] = base + cnt;
}

// ---------------------------------------------------------------------------
// Projection body, templated on NMAT.
//   NMAT=3: gathered UNMASKED rows -> Q (scattered to orig rows) + K,V (compact)
//   NMAT=1: gathered MASKED rows   -> Q only (scattered to orig rows)
// BM=64, BK=32, 256 threads (8 warps: 4 M x 2 N). W planes via cp.async
// double-buffer; x rows via f32 register prefetch + in-register bf16 split.
// ---------------------------------------------------------------------------
#define QP 40
#define XPL (64 * QP)            // u16 per plane
#define XSTG (2 * XPL)
#define WBASE (2 * XSTG)
#define PROJ_SMEM_BYTES ((WBASE + 2 * 6 * XPL) * 2)   // sized for NMAT=3

template<int NMAT>
__device__ __forceinline__ void proj_body(
    unsigned short* qsm, const float* __restrict__ x,
    const float* __restrict__ bq, const float* __restrict__ bk,
    const float* __restrict__ bv,
    int b, int j0, int cnt, const int* __restrict__ list)
{
    constexpr int WSTGP = 2 * NMAT;

    const int t = threadIdx.x;
    const int warp = t >> 5, lane = t & 31;
    const int wm = warp >> 1;
    const int wn = warp & 1;

    float acc[NMAT][4][4] = {};

    const int arow = wm * 16 + (lane & 15);
    const int acol = (lane >> 4) * 8;
    const int brow = (lane & 7) + ((lane >> 4) << 3);
    const int bcol = ((lane >> 3) & 1) * 8;

    const int xr = t >> 2;             // staged row within tile
    const int xc = (t & 3) * 8;        // f32 col base

    // gather source row (clamped tail -> duplicate rows, consistent outputs)
    int jg = j0 + xr;
    if (jg > cnt - 1) jg = cnt - 1;
    const float* xrow = x + ((size_t)b * SS + list[jg]) * EE;

    // W stage s for k-slab: 2*NMAT planes x 256 chunks of 16B (R5-proven map)
    auto issue_w = [&](int s, int slab) {
        #pragma unroll
        for (int i = 0; i < 2 * NMAT; i++) {
            int chunk = t + i * 256;
            int p = chunk >> 8, c = chunk & 255;
            int row = c >> 2, c4 = c & 3;
            uint32_t dst = smem_u32(&qsm[WBASE + (s * WSTGP + p) * XPL + row * QP + c4 * 8]);
            const unsigned int* srcp = (p & 1) ? g_Wl : g_Wh;
            cp16(dst, srcp + ((size_t)(p >> 1) * 32768
                              + (size_t)row * 512 + slab * 16 + c4 * 4));
        }
        asm volatile("cp.async.commit_group;");
    };

    auto sts_x = [&](int s, float4 a0, float4 a1) {
        unsigned short* Xh = qsm + s * XSTG;
        unsigned short* Xl = Xh + XPL;
        uint32_t h, l;
        split_pair(a0.x, a0.y, h, l);
        *(uint32_t*)&Xh[xr * QP + xc]     = h; *(uint32_t*)&Xl[xr * QP + xc]     = l;
        split_pair(a0.z, a0.w, h, l);
        *(uint32_t*)&Xh[xr * QP + xc + 2] = h; *(uint32_t*)&Xl[xr * QP + xc + 2] = l;
        split_pair(a1.x, a1.y, h, l);
        *(uint32_t*)&Xh[xr * QP + xc + 4] = h; *(uint32_t*)&Xl[xr * QP + xc + 4] = l;
        split_pair(a1.z, a1.w, h, l);
        *(uint32_t*)&Xh[xr * QP + xc + 6] = h; *(uint32_t*)&Xl[xr * QP + xc + 6] = l;
    };

    issue_w(0, 0);
    {
        float4 a0 = *reinterpret_cast<const float4*>(&xrow[xc]);
        float4 a1 = *reinterpret_cast<const float4*>(&xrow[xc + 4]);
        sts_x(0, a0, a1);
    }
    float4 xa0 = *reinterpret_cast<const float4*>(&xrow[32 + xc]);
    float4 xa1 = *reinterpret_cast<const float4*>(&xrow[32 + xc + 4]);

    const int NI = EE / 32;
    for (int i = 0; i < NI; i++) {
        const int s = i & 1;

        asm volatile("cp.async.wait_group 0;");
        __syncthreads();

        if (i + 1 < NI) {
            issue_w(s ^ 1, i + 1);
            sts_x(s ^ 1, xa0, xa1);
            if (i + 2 < NI) {
                int kn = (i + 2) * 32;
                xa0 = *reinterpret_cast<const float4*>(&xrow[kn + xc]);
                xa1 = *reinterpret_cast<const float4*>(&xrow[kn + xc + 4]);
            }
        }

        const unsigned short* Xh = qsm + s * XSTG;
        const unsigned short* Xl = Xh + XPL;
        const unsigned short* Wb = qsm + WBASE + s * WSTGP * XPL;

        #pragma unroll
        for (int ks = 0; ks < 2; ks++) {
            uint32_t ah[4], al[4];
            ldsm_x4(smem_u32(&Xh[arow * QP + ks * 16 + acol]), ah[0], ah[1], ah[2], ah[3]);
            ldsm_x4(smem_u32(&Xl[arow * QP + ks * 16 + acol]), al[0], al[1], al[2], al[3]);
            #pragma unroll
            for (int mm = 0; mm < NMAT; mm++) {
                const unsigned short* Wh = Wb + (mm * 2) * XPL;
                const unsigned short* Wl = Wh + XPL;
                #pragma unroll
                for (int pr = 0; pr < 2; pr++) {
                    uint32_t bh0, bh1, bh2, bh3, bl0, bl1, bl2, bl3;
                    ldsm_x4(smem_u32(&Wh[(wn * 32 + pr * 16 + brow) * QP + ks * 16 + bcol]),
                            bh0, bh1, bh2, bh3);
                    ldsm_x4(smem_u32(&Wl[(wn * 32 + pr * 16 + brow) * QP + ks * 16 + bcol]),
                            bl0, bl1, bl2, bl3);
                    float* c0 = acc[mm][pr * 2];
                    float* c1 = acc[mm][pr * 2 + 1];
                    mma_bf16(c0, ah[0], ah[1], ah[2], ah[3], bh0, bh1);
                    mma_bf16(c0, ah[0], ah[1], ah[2], ah[3], bl0, bl1);
                    mma_bf16(c0, al[0], al[1], al[2], al[3], bh0, bh1);
                    mma_bf16(c1, ah[0], ah[1], ah[2], ah[3], bh2, bh3);
                    mma_bf16(c1, ah[0], ah[1], ah[2], ah[3], bl2, bl3);
                    mma_bf16(c1, al[0], al[1], al[2], al[3], bh2, bh3);
                }
            }
        }
    }

    // epilogue: Q (mm=0) scattered to original rows; K/V (mm=1,2) compacted
    int jr0 = j0 + wm * 16 + (lane >> 2);
    int jr8 = jr0 + 8;
    if (jr0 > cnt - 1) jr0 = cnt - 1;
    if (jr8 > cnt - 1) jr8 = cnt - 1;
    const size_t qrow0 = (size_t)b * SS + list[jr0];
    const size_t qrow8 = (size_t)b * SS + list[jr8];

    #pragma unroll
    for (int mm = 0; mm < NMAT; mm++) {
        const float* bias = (mm == 0) ? bq : (mm == 1) ? bk : bv;
        unsigned int* gh = (mm == 0) ? g_qh : (mm == 1) ? g_kh : g_vh;
        unsigned int* gl = (mm == 0) ? g_ql : (mm == 1) ? g_kl : g_vl;
        size_t r0, r8;
        if (mm == 0) { r0 = qrow0; r8 = qrow8; }
        else {
            r0 = (size_t)b * SS + j0 + wm * 16 + (lane >> 2);
            r8 = r0 + 8;
        }
        #pragma unroll
        for (int na = 0; na < 4; na++) {
            int col = wn * 32 + na * 8 + (lane & 3) * 2;
            float b0 = bias[col], b1 = bias[col + 1];
            float c0 = acc[mm][na][0] + b0, c1 = acc[mm][na][1] + b1;
            float c2 = acc[mm][na][2] + b0, c3 = acc[mm][na][3] + b1;
            uint32_t h, l;
            split_pair(c0, c1, h, l);
            gh[r0 * 32 + col / 2] = h;
            gl[r0 * 32 + col / 2] = l;
            split_pair(c2, c3, h, l);
            gh[r8 * 32 + col / 2] = h;
            gl[r8 * 32 + col / 2] = l;
        }
    }
}

__global__ __launch_bounds__(256) void proj_kernel(
    const float* __restrict__ x,
    const float* __restrict__ bq, const float* __restrict__ bk,
    const float* __restrict__ bv)
{
    extern __shared__ unsigned short qsm[];
    const int b = blockIdx.y;
    const int j0 = blockIdx.x * 64;
    const int nk = g_kcnt[b];

    if (blockIdx.z == 0) {
        if (j0 >= nk) return;
        proj_body<3>(qsm, x, bq, bk, bv, b, j0, nk, g_kidx[b]);
    } else {
        const int nm = SS - nk;
        if (j0 >= nm || nm == 0) return;
        proj_body<1>(qsm, x, bq, bk, bv, b, j0, nm, g_midx[b]);
    }
}

// ---------------------------------------------------------------------------
// Flash attention over COMPACTED keys (contiguous), split-KV x3.
// (unchanged from R9 — proven)
// ---------------------------------------------------------------------------
#define KP 72
#define TILE_U16 (64 * KP)
#define STAGE_U16 (4 * TILE_U16)
#define ATTN_SMEM_BYTES (2 * STAGE_U16 * 2 + 64 * 4)

__device__ __forceinline__ void stage_tile(uint32_t sbase, size_t gbase, int t) {
    #pragma unroll
    for (int i = 0; i < 4; i++) {
        int chunk = t + i * 128;
        int r = chunk >> 3, c = chunk & 7;
        uint32_t soff = (uint32_t)(r * KP + c * 8) * 2;
        size_t goff = (size_t)r * 32 + c * 4;
        cp16(sbase + soff,                     g_kh + gbase + goff);
        cp16(sbase + TILE_U16 * 2 + soff,      g_kl + gbase + goff);
        cp16(sbase + 2 * TILE_U16 * 2 + soff,  g_vh + gbase + goff);
        cp16(sbase + 3 * TILE_U16 * 2 + soff,  g_vl + gbase + goff);
    }
    asm volatile("cp.async.commit_group;");
}

__global__ __launch_bounds__(128, 3) void attn_kernel()
{
    extern __shared__ unsigned short sm[];
    float* ms = (float*)(sm + 2 * STAGE_U16);

    const int t = threadIdx.x, warp = t >> 5, lane = t & 31;
    const int b = blockIdx.y, q0 = blockIdx.x * 64;
    const int seg = blockIdx.z;

    const int nk = g_kcnt[b];
    const int T = (nk + 63) >> 6;
    const int bnt = T / 3, rem = T - bnt * 3;
    const int nt = bnt + (seg < rem ? 1 : 0);
    const int t0 = seg * bnt + (seg < rem ? seg : rem);

    // --- stage Q into stage-0, extract fragments ---
    {
        uint32_t s0 = smem_u32(sm);
        size_t gq = ((size_t)b * SS + q0) * 32;
        #pragma unroll
        for (int i = 0; i < 4; i++) {
            int chunk = t + i * 128;
            int r = chunk >> 3, c = chunk & 7;
            uint32_t soff = (uint32_t)(r * KP + c * 8) * 2;
            size_t goff = (size_t)r * 32 + c * 4;
            cp16(s0 + soff,                g_qh + gq + goff);
            cp16(s0 + TILE_U16 * 2 + soff, g_ql + gq + goff);
        }
        asm volatile("cp.async.commit_group;");
        asm volatile("cp.async.wait_group 0;");
        __syncthreads();
    }

    uint32_t qh[4][4], ql[4][4];
    {
        const int arow = warp * 16 + (lane & 15);
        const int acol = (lane >> 4) * 8;
        #pragma unroll
        for (int ks = 0; ks < 4; ks++) {
            ldsm_x4(smem_u32(&sm[arow * KP + ks * 16 + acol]),
                    qh[ks][0], qh[ks][1], qh[ks][2], qh[ks][3]);
            ldsm_x4(smem_u32(&sm[TILE_U16 + arow * KP + ks * 16 + acol]),
                    ql[ks][0], ql[ks][1], ql[ks][2], ql[ks][3]);
        }
    }
    __syncthreads();

    float O[8][4] = {};
    float m0r = -INFINITY, m1r = -INFINITY, l0r = 0.f, l1r = 0.f;
    const float scale = 0.125f;

    const uint32_t stage_addr[2] = { smem_u32(sm), smem_u32(sm + STAGE_U16) };

    if (nt > 0) {
        stage_tile(stage_addr[0], ((size_t)b * SS + t0 * 64) * 32, t);

        const int brow = (lane & 7) + ((lane >> 4) << 3);
        const int bco  = ((lane >> 3) & 1) * 8;
        const int vrow = lane & 15;
        const int vco  = (lane >> 4) * 8;

        for (int it = 0; it < nt; ++it) {
            const int st = it & 1;
            const unsigned short* Kh = sm + st * STAGE_U16;
            const unsigned short* Kl = Kh + TILE_U16;
            const unsigned short* Vh = Kh + 2 * TILE_U16;
            const unsigned short* Vl = Kh + 3 * TILE_U16;

            if (it + 1 < nt)
                stage_tile(stage_addr[st ^ 1], ((size_t)b * SS + (t0 + it + 1) * 64) * 32, t);
            if (t < 64) ms[t] = ((t0 + it) * 64 + t < nk) ? 0.f : -INFINITY;

            if (it + 1 < nt) asm volatile("cp.async.wait_group 1;");
            else             asm volatile("cp.async.wait_group 0;");
            __syncthreads();

            // --- S = Q K^T ---
            float S[8][4] = {};
            #pragma unroll
            for (int ks = 0; ks < 4; ks++) {
                #pragma unroll
                for (int pr = 0; pr < 4; pr++) {
                    uint32_t bh0, bh1, bh2, bh3, bl0, bl1, bl2, bl3;
                    ldsm_x4(smem_u32(&Kh[(pr * 16 + brow) * KP + ks * 16 + bco]),
                            bh0, bh1, bh2, bh3);
                    ldsm_x4(smem_u32(&Kl[(pr * 16 + brow) * KP + ks * 16 + bco]),
                            bl0, bl1, bl2, bl3);
                    float* s0 = S[pr * 2];
                    float* s1 = S[pr * 2 + 1];
                    mma_bf16(s0, qh[ks][0], qh[ks][1], qh[ks][2], qh[ks][3], bh0, bh1);
                    mma_bf16(s0, qh[ks][0], qh[ks][1], qh[ks][2], qh[ks][3], bl0, bl1);
                    mma_bf16(s0, ql[ks][0], ql[ks][1], ql[ks][2], ql[ks][3], bh0, bh1);
                    mma_bf16(s1, qh[ks][0], qh[ks][1], qh[ks][2], qh[ks][3], bh2, bh3);
                    mma_bf16(s1, qh[ks][0], qh[ks][1], qh[ks][2], qh[ks][3], bl2, bl3);
                    mma_bf16(s1, ql[ks][0], ql[ks][1], ql[ks][2], ql[ks][3], bh2, bh3);
                }
            }

            // --- online softmax ---
            float rmax0 = -INFINITY, rmax1 = -INFINITY;
            #pragma unroll
            for (int na = 0; na < 8; na++) {
                int col = na * 8 + (lane & 3) * 2;
                float ma = ms[col], mb = ms[col + 1];
                S[na][0] = S[na][0] * scale + ma;
                S[na][1] = S[na][1] * scale + mb;
                S[na][2] = S[na][2] * scale + ma;
                S[na][3] = S[na][3] * scale + mb;
                rmax0 = fmaxf(rmax0, fmaxf(S[na][0], S[na][1]));
                rmax1 = fmaxf(rmax1, fmaxf(S[na][2], S[na][3]));
            }
            rmax0 = fmaxf(rmax0, __shfl_xor_sync(0xffffffffu, rmax0, 1));
            rmax0 = fmaxf(rmax0, __shfl_xor_sync(0xffffffffu, rmax0, 2));
            rmax1 = fmaxf(rmax1, __shfl_xor_sync(0xffffffffu, rmax1, 1));
            rmax1 = fmaxf(rmax1, __shfl_xor_sync(0xffffffffu, rmax1, 2));

            float nm0 = fmaxf(m0r, rmax0), nm1 = fmaxf(m1r, rmax1);
            float f0 = (m0r == -INFINITY) ? 0.f : __expf(m0r - nm0);
            float f1 = (m1r == -INFINITY) ? 0.f : __expf(m1r - nm1);
            float rs0 = 0.f, rs1 = 0.f;
            #pragma unroll
            for (int na = 0; na < 8; na++) {
                float p0 = __expf(S[na][0] - nm0); p0 = (S[na][0] == -INFINITY) ? 0.f : p0;
                float p1 = __expf(S[na][1] - nm0); p1 = (S[na][1] == -INFINITY) ? 0.f : p1;
                float p2 = __expf(S[na][2] - nm1); p2 = (S[na][2] == -INFINITY) ? 0.f : p2;
                float p3 = __expf(S[na][3] - nm1); p3 = (S[na][3] == -INFINITY) ? 0.f : p3;
                S[na][0] = p0; S[na][1] = p1; S[na][2] = p2; S[na][3] = p3;
                rs0 += p0 + p1; rs1 += p2 + p3;
            }
            rs0 += __shfl_xor_sync(0xffffffffu, rs0, 1);
            rs0 += __shfl_xor_sync(0xffffffffu, rs0, 2);
            rs1 += __shfl_xor_sync(0xffffffffu, rs1, 1);
            rs1 += __shfl_xor_sync(0xffffffffu, rs1, 2);
            l0r = l0r * f0 + rs0;  m0r = nm0;
            l1r = l1r * f1 + rs1;  m1r = nm1;

            #pragma unroll
            for (int na = 0; na < 8; na++) {
                O[na][0] *= f0; O[na][1] *= f0;
                O[na][2] *= f1; O[na][3] *= f1;
            }

            // --- O += P V ---
            #pragma unroll
            for (int kk = 0; kk < 4; kk++) {
                uint32_t ph[4], pl[4];
                split_pair(S[2 * kk][0],     S[2 * kk][1],     ph[0], pl[0]);
                split_pair(S[2 * kk][2],     S[2 * kk][3],     ph[1], pl[1]);
                split_pair(S[2 * kk + 1][0], S[2 * kk + 1][1], ph[2], pl[2]);
                split_pair(S[2 * kk + 1][2], S[2 * kk + 1][3], ph[3], pl[3]);
                #pragma unroll
                for (int pr = 0; pr < 4; pr++) {
                    uint32_t bh0, bh1, bh2, bh3, bl0, bl1, bl2, bl3;
                    ldsm_x4_t(smem_u32(&Vh[(kk * 16 + vrow) * KP + pr * 16 + vco]),
                              bh0, bh1, bh2, bh3);
                    ldsm_x4_t(smem_u32(&Vl[(kk * 16 + vrow) * KP + pr * 16 + vco]),
                              bl0, bl1, bl2, bl3);
                    float* o0 = O[pr * 2];
                    float* o1 = O[pr * 2 + 1];
                    mma_bf16(o0, ph[0], ph[1], ph[2], ph[3], bh0, bh1);
                    mma_bf16(o0, ph[0], ph[1], ph[2], ph[3], bl0, bl1);
                    mma_bf16(o0, pl[0], pl[1], pl[2], pl[3], bh0, bh1);
                    mma_bf16(o1, ph[0], ph[1], ph[2], ph[3], bh2, bh3);
                    mma_bf16(o1, ph[0], ph[1], ph[2], ph[3], bl2, bl3);
                    mma_bf16(o1, pl[0], pl[1], pl[2], pl[3], bh2, bh3);
                }
            }
            __syncthreads();
        }
    }

    // --- store UNNORMALIZED partials + (m,l) ---
    int row0 = q0 + warp * 16 + (lane >> 2);
    float* Op = g_Op[seg];
    #pragma unroll
    for (int na = 0; na < 8; na++) {
        int col = na * 8 + (lane & 3) * 2;
        *(float2*)&Op[((size_t)b * SS + row0) * DD + col] =
            make_float2(O[na][0], O[na][1]);
        *(float2*)&Op[((size_t)b * SS + row0 + 8) * DD + col] =
            make_float2(O[na][2], O[na][3]);
    }
    if ((lane & 3) == 0) {
        size_t r = (size_t)b * SS + row0;
        g_mp[seg][r] = m0r;     g_lp[seg][r] = l0r;
        g_mp[seg][r + 8] = m1r; g_lp[seg][r + 8] = l1r;
    }
}

// ---------------------------------------------------------------------------
// combine split-KV partials (3-way)
// ---------------------------------------------------------------------------
__global__ void combine_kernel(float* __restrict__ out) {
    int idx = blockIdx.x * 256 + threadIdx.x;
    int row = idx >> 4;
    float m0 = g_mp[0][row], m1 = g_mp[1][row], m2 = g_mp[2][row];
    float M = fmaxf(fmaxf(m0, m1), m2);
    float w0 = (m0 == -INFINITY) ? 0.f : __expf(m0 - M);
    float w1 = (m1 == -INFINITY) ? 0.f : __expf(m1 - M);
    float w2 = (m2 == -INFINITY) ? 0.f : __expf(m2 - M);
    float inv = 1.f / (w0 * g_lp[0][row] + w1 * g_lp[1][row] + w2 * g_lp[2][row]);
    float a0 = w0 * inv, a1 = w1 * inv, a2 = w2 * inv;
    float4 o0 = reinterpret_cast<const float4*>(g_Op[0])[idx];
    float4 o1 = reinterpret_cast<const float4*>(g_Op[1])[idx];
    float4 o2 = reinterpret_cast<const float4*>(g_Op[2])[idx];
    float4 r;
    r.x = o0.x * a0 + o1.x * a1 + o2.x * a2;
    r.y = o0.y * a0 + o1.y * a1 + o2.y * a2;
    r.z = o0.z * a0 + o1.z * a1 + o2.z * a2;
    r.w = o0.w * a0 + o1.w * a1 + o2.w * a2;
    reinterpret_cast<float4*>(out)[idx] = r;
}

// ---------------------------------------------------------------------------
// Launch
// ---------------------------------------------------------------------------
extern "C" void kernel_launch(void* const* d_in, const int* in_sizes, int n_in,
                              void* d_out, int out_size) {
    const float* x  = (const float*)d_in[0];
    const float* Wq = (const float*)d_in[1];
    const float* bq = (const float*)d_in[2];
    const float* Wk = (const float*)d_in[3];
    const float* bk = (const float*)d_in[4];
    const float* Wv = (const float*)d_in[5];
    const float* bv = (const float*)d_in[6];
    const int*   pm = (const int*)d_in[7];
    float* out = (float*)d_out;

    prep_w<<<3 * 64 * 512 / 256, 256>>>(Wq, Wk, Wv);
    prep_mask<<<BB, 256>>>(pm);

    cudaFuncSetAttribute(proj_kernel, cudaFuncAttributeMaxDynamicSharedMemorySize,
                         PROJ_SMEM_BYTES);
    proj_kernel<<<dim3(SS / 64, BB, 2), 256, PROJ_SMEM_BYTES>>>(x, bq, bk, bv);

    cudaFuncSetAttribute(attn_kernel, cudaFuncAttributeMaxDynamicSharedMemorySize,
                         ATTN_SMEM_BYTES);
    attn_kernel<<<dim3(SS / 64, BB, NSEG), 128, ATTN_SMEM_BYTES>>>();

    combine_kernel<<<BB * SS * DD / 4 / 256, 256>>>(out);
}